// round 4
// baseline (speedup 1.0000x reference)
#include <cuda_runtime.h>
#include <cuda_bf16.h>
#include <cstdint>

#define NN 100000
#define EE 1600000
#define NEG_SLOPE 0.2f
#define LN_EPS 1e-5f
#define NCHUNK 98  // ceil(NN/1024)

// ---------------- scratch (device globals; no allocation allowed) ----------------
__device__ float  g_feat[(size_t)NN * 128];   // h @ W  (51.2 MB, mostly L2-resident)
__device__ float  g_el[NN * 2];
__device__ float  g_er[NN * 2];
__device__ int    g_deg[NN];
__device__ int    g_rowptr[NN + 1];
__device__ int    g_cursor[NN];
__device__ int    g_chunk_sum[128];
__device__ int    g_chunk_excl[128];
__device__ float4 g_csr[EE];                  // {src(bits), exp_e_head0, exp_e_head1, pad}

// ---------------- 0: zero degree counters ----------------
__global__ void zero_deg_kernel() {
    int i = blockIdx.x * blockDim.x + threadIdx.x;
    if (i < NN) g_deg[i] = 0;
}

// ================= tensor-core GEMM via mma.sync (HMMA, arch-baseline PTX) =================
// feat = h@W + el/er dots. Split-precision bf16: D = Ahi*Bhi + Alo*Bhi + Ahi*Blo (fp32 accum).
// CTA = 128 rows x 128 cols, K=128 staged fully in smem.
// smem rows padded to 136 bf16 (272 B) -> fragment LDS bank-conflict-free.
#define ASTR 272                 // bytes per padded bf16 row (136 halves)
#define SM_A_HI 0                // 128*272 = 34816
#define SM_A_LO 34816
#define SM_B_HI 69632            // Wt[n][k], padded
#define SM_B_LO 104448
#define SM_ATTN_L 139264
#define SM_ATTN_R 139776
#define SM_TOTAL 140288

__device__ __forceinline__ uint32_t pack_bf16(float a, float b) {
    __nv_bfloat162 t = __floats2bfloat162_rn(a, b);
    return *reinterpret_cast<uint32_t*>(&t);
}
__device__ __forceinline__ void mma_bf16(float* d, uint32_t a0, uint32_t a1, uint32_t a2,
                                         uint32_t a3, uint32_t b0, uint32_t b1) {
    asm volatile(
        "mma.sync.aligned.m16n8k16.row.col.f32.bf16.bf16.f32 "
        "{%0,%1,%2,%3}, {%4,%5,%6,%7}, {%8,%9}, {%0,%1,%2,%3};"
        : "+f"(d[0]), "+f"(d[1]), "+f"(d[2]), "+f"(d[3])
        : "r"(a0), "r"(a1), "r"(a2), "r"(a3), "r"(b0), "r"(b1));
}

__global__ void __launch_bounds__(256) gemm_tc_kernel(const float* __restrict__ h,
                                                      const float* __restrict__ W,
                                                      const float* __restrict__ attn_l,
                                                      const float* __restrict__ attn_r) {
    extern __shared__ char smem[];
    int tid = threadIdx.x;
    int lane = tid & 31, wid = tid >> 5;
    int row0 = blockIdx.x * 128;

    // ---- stage attn ----
    if (tid < 128) {
        *(float*)(smem + SM_ATTN_L + tid * 4) = attn_l[tid];
        *(float*)(smem + SM_ATTN_R + tid * 4) = attn_r[tid];
    }
    // ---- stage A = h rows (hi/lo bf16), padded, zero-filled OOB ----
    for (int job = tid; job < 128 * 32; job += 256) {
        int r = job >> 5, c4 = job & 31;
        int grow = row0 + r;
        float4 v = make_float4(0.f, 0.f, 0.f, 0.f);
        if (grow < NN) v = *(const float4*)(h + (size_t)grow * 128 + c4 * 4);
        __nv_bfloat16 h0 = __float2bfloat16(v.x), h1 = __float2bfloat16(v.y);
        __nv_bfloat16 h2 = __float2bfloat16(v.z), h3 = __float2bfloat16(v.w);
        uint2 hiv, lov;
        hiv.x = pack_bf16(__bfloat162float(h0), __bfloat162float(h1));
        hiv.y = pack_bf16(__bfloat162float(h2), __bfloat162float(h3));
        lov.x = pack_bf16(v.x - __bfloat162float(h0), v.y - __bfloat162float(h1));
        lov.y = pack_bf16(v.z - __bfloat162float(h2), v.w - __bfloat162float(h3));
        uint32_t off = (uint32_t)r * ASTR + c4 * 8;
        *(uint2*)(smem + SM_A_HI + off) = hiv;
        *(uint2*)(smem + SM_A_LO + off) = lov;
    }
    // ---- stage B = W transposed: Bt[n][k] = W[k][n] (hi/lo bf16) ----
    for (int job = tid; job < 128 * 32; job += 256) {
        int k = job >> 5, c4 = job & 31;
        float4 v = *(const float4*)(W + (size_t)k * 128 + c4 * 4);
        float vv[4] = {v.x, v.y, v.z, v.w};
#pragma unroll
        for (int i = 0; i < 4; i++) {
            int n = c4 * 4 + i;
            __nv_bfloat16 hb = __float2bfloat16(vv[i]);
            uint32_t off = (uint32_t)n * ASTR + k * 2;
            *(__nv_bfloat16*)(smem + SM_B_HI + off) = hb;
            *(__nv_bfloat16*)(smem + SM_B_LO + off) = __float2bfloat16(vv[i] - __bfloat162float(hb));
        }
    }
    __syncthreads();

    // ---- MMA mainloop: warp owns rows [wid*16, wid*16+16), all 128 cols ----
    int g = lane >> 2, tg = lane & 3;
    const char* Arow_hi = smem + SM_A_HI + (uint32_t)(wid * 16 + g) * ASTR;
    const char* Arow_lo = smem + SM_A_LO + (uint32_t)(wid * 16 + g) * ASTR;
    float d[16][4];
#pragma unroll
    for (int nt = 0; nt < 16; nt++) { d[nt][0] = d[nt][1] = d[nt][2] = d[nt][3] = 0.f; }

#pragma unroll
    for (int ks = 0; ks < 8; ks++) {
        uint32_t kb = ks * 32 + tg * 4;
        uint32_t ah0 = *(const uint32_t*)(Arow_hi + kb);
        uint32_t ah1 = *(const uint32_t*)(Arow_hi + 8 * ASTR + kb);
        uint32_t ah2 = *(const uint32_t*)(Arow_hi + kb + 16);
        uint32_t ah3 = *(const uint32_t*)(Arow_hi + 8 * ASTR + kb + 16);
        uint32_t al0 = *(const uint32_t*)(Arow_lo + kb);
        uint32_t al1 = *(const uint32_t*)(Arow_lo + 8 * ASTR + kb);
        uint32_t al2 = *(const uint32_t*)(Arow_lo + kb + 16);
        uint32_t al3 = *(const uint32_t*)(Arow_lo + 8 * ASTR + kb + 16);
#pragma unroll
        for (int nt = 0; nt < 16; nt++) {
            uint32_t nb = (uint32_t)(nt * 8 + g) * ASTR + kb;
            uint32_t bh0 = *(const uint32_t*)(smem + SM_B_HI + nb);
            uint32_t bh1 = *(const uint32_t*)(smem + SM_B_HI + nb + 16);
            uint32_t bl0 = *(const uint32_t*)(smem + SM_B_LO + nb);
            uint32_t bl1 = *(const uint32_t*)(smem + SM_B_LO + nb + 16);
            mma_bf16(d[nt], ah0, ah1, ah2, ah3, bh0, bh1);
            mma_bf16(d[nt], al0, al1, al2, al3, bh0, bh1);
            mma_bf16(d[nt], ah0, ah1, ah2, ah3, bl0, bl1);
        }
    }

    // ---- epilogue: store feat fragments + attn dots ----
    int r0 = row0 + wid * 16 + g;
    int r1 = r0 + 8;
    float el0h0 = 0.f, el0h1 = 0.f, er0h0 = 0.f, er0h1 = 0.f;
    float el1h0 = 0.f, el1h1 = 0.f, er1h0 = 0.f, er1h1 = 0.f;
    const float* alp = (const float*)(smem + SM_ATTN_L);
    const float* arp = (const float*)(smem + SM_ATTN_R);
#pragma unroll
    for (int nt = 0; nt < 16; nt++) {
        int c = nt * 8 + tg * 2;
        float a0 = alp[c], a1 = alp[c + 1], b0 = arp[c], b1 = arp[c + 1];
        float p0 = d[nt][0] * a0 + d[nt][1] * a1;   // row r0, el partial
        float q0 = d[nt][0] * b0 + d[nt][1] * b1;   // row r0, er partial
        float p1 = d[nt][2] * a0 + d[nt][3] * a1;   // row r1
        float q1 = d[nt][2] * b0 + d[nt][3] * b1;
        if (nt < 8) { el0h0 += p0; er0h0 += q0; el1h0 += p1; er1h0 += q1; }
        else        { el0h1 += p0; er0h1 += q0; el1h1 += p1; er1h1 += q1; }
        if (r0 < NN) *(float2*)(g_feat + (size_t)r0 * 128 + c) = make_float2(d[nt][0], d[nt][1]);
        if (r1 < NN) *(float2*)(g_feat + (size_t)r1 * 128 + c) = make_float2(d[nt][2], d[nt][3]);
    }
    // reduce across the 4 lanes of the quad (same g)
#pragma unroll
    for (int off = 1; off <= 2; off <<= 1) {
        el0h0 += __shfl_xor_sync(0xffffffffu, el0h0, off);
        el0h1 += __shfl_xor_sync(0xffffffffu, el0h1, off);
        er0h0 += __shfl_xor_sync(0xffffffffu, er0h0, off);
        er0h1 += __shfl_xor_sync(0xffffffffu, er0h1, off);
        el1h0 += __shfl_xor_sync(0xffffffffu, el1h0, off);
        el1h1 += __shfl_xor_sync(0xffffffffu, el1h1, off);
        er1h0 += __shfl_xor_sync(0xffffffffu, er1h0, off);
        er1h1 += __shfl_xor_sync(0xffffffffu, er1h1, off);
    }
    if (tg == 0) {
        if (r0 < NN) {
            g_el[2 * r0] = el0h0; g_el[2 * r0 + 1] = el0h1;
            g_er[2 * r0] = er0h0; g_er[2 * r0 + 1] = er0h1;
        }
        if (r1 < NN) {
            g_el[2 * r1] = el1h0; g_el[2 * r1 + 1] = el1h1;
            g_er[2 * r1] = er1h0; g_er[2 * r1 + 1] = er1h1;
        }
    }
}

// ---------------- 2: degree histogram ----------------
__global__ void hist_kernel(const int* __restrict__ dst) {
    int e = blockIdx.x * blockDim.x + threadIdx.x;
    if (e < EE) atomicAdd(&g_deg[dst[e]], 1);
}

// ---------------- 3a: per-chunk sums (chunk = 1024) ----------------
__global__ void chunk_sum_kernel() {
    int b = blockIdx.x, t = threadIdx.x;
    int base = b * 1024;
    int s = 0;
    for (int j = t; j < 1024; j += 256) {
        int i = base + j;
        s += (i < NN) ? g_deg[i] : 0;
    }
    __shared__ int sh[8];
#pragma unroll
    for (int off = 16; off; off >>= 1) s += __shfl_xor_sync(0xffffffffu, s, off);
    if ((t & 31) == 0) sh[t >> 5] = s;
    __syncthreads();
    if (t < 32) {
        int v = (t < 8) ? sh[t] : 0;
#pragma unroll
        for (int off = 4; off; off >>= 1) v += __shfl_xor_sync(0xffffffffu, v, off);
        if (t == 0) g_chunk_sum[b] = v;
    }
}

// ---------------- 3b: scan chunk sums (1 block) ----------------
__global__ void scan_chunks_kernel() {
    __shared__ int sh[128];
    int t = threadIdx.x;
    int v = (t < NCHUNK) ? g_chunk_sum[t] : 0;
    sh[t] = v;
    __syncthreads();
    for (int off = 1; off < 128; off <<= 1) {
        int a = (t >= off) ? sh[t - off] : 0;
        __syncthreads();
        sh[t] += a;
        __syncthreads();
    }
    if (t < NCHUNK) g_chunk_excl[t] = sh[t] - v;
}

// ---------------- 3c: finalize row_ptr / cursor ----------------
__global__ void scan_final_kernel() {
    int i = blockIdx.x * 1024 + threadIdx.x;
    int lane = threadIdx.x & 31, wid = threadIdx.x >> 5;
    int v = (i < NN) ? g_deg[i] : 0;
    int x = v;
#pragma unroll
    for (int off = 1; off < 32; off <<= 1) {
        int y = __shfl_up_sync(0xffffffffu, x, off);
        if (lane >= off) x += y;
    }
    __shared__ int sh[32];
    if (lane == 31) sh[wid] = x;
    __syncthreads();
    if (wid == 0) {
        int y = sh[lane];
#pragma unroll
        for (int off = 1; off < 32; off <<= 1) {
            int z = __shfl_up_sync(0xffffffffu, y, off);
            if (lane >= off) y += z;
        }
        sh[lane] = y;
    }
    __syncthreads();
    int incl = x + (wid ? sh[wid - 1] : 0);
    int base = g_chunk_excl[blockIdx.x];
    if (i < NN) {
        int excl = base + incl - v;
        g_rowptr[i] = excl;
        g_cursor[i] = excl;
    }
    if (i == NN - 1) g_rowptr[NN] = base + incl;
}

// ---------------- 4: scatter edges into CSR order with exp(logit) ----------------
__global__ void scatter_kernel(const int* __restrict__ src, const int* __restrict__ dst) {
    int e = blockIdx.x * blockDim.x + threadIdx.x;
    if (e >= EE) return;
    int s = src[e], d = dst[e];
    int p = atomicAdd(&g_cursor[d], 1);
    float e0 = g_el[2 * s]     + g_er[2 * d];
    float e1 = g_el[2 * s + 1] + g_er[2 * d + 1];
    e0 = (e0 > 0.f) ? e0 : NEG_SLOPE * e0;
    e1 = (e1 > 0.f) ? e1 : NEG_SLOPE * e1;
    g_csr[p] = make_float4(__int_as_float(s), __expf(e0), __expf(e1), 0.f);
}

// ---------------- 5: per-node weighted aggregate + fused LayerNorm ----------------
__global__ void agg_ln_kernel(const float* __restrict__ bias, const float* __restrict__ gamma,
                              const float* __restrict__ beta, float* __restrict__ out) {
    int gwarp = (blockIdx.x * blockDim.x + threadIdx.x) >> 5;
    int lane = threadIdx.x & 31;
    if (gwarp >= NN) return;
    int beg = g_rowptr[gwarp], end = g_rowptr[gwarp + 1];
    bool h1 = (lane >= 16);

    float4 acc = make_float4(0.f, 0.f, 0.f, 0.f);
    float wsum = 0.f;
    int i = beg;
    for (; i + 2 <= end; i += 2) {
        float4 c0 = g_csr[i], c1 = g_csr[i + 1];
        const float4* p0 = (const float4*)(g_feat + (size_t)__float_as_int(c0.x) * 128);
        const float4* p1 = (const float4*)(g_feat + (size_t)__float_as_int(c1.x) * 128);
        float4 v0 = p0[lane], v1 = p1[lane];
        float w0 = h1 ? c0.z : c0.y;
        float w1 = h1 ? c1.z : c1.y;
        wsum += w0 + w1;
        acc.x += w0 * v0.x + w1 * v1.x;
        acc.y += w0 * v0.y + w1 * v1.y;
        acc.z += w0 * v0.z + w1 * v1.z;
        acc.w += w0 * v0.w + w1 * v1.w;
    }
    if (i < end) {
        float4 c0 = g_csr[i];
        const float4* p0 = (const float4*)(g_feat + (size_t)__float_as_int(c0.x) * 128);
        float4 v0 = p0[lane];
        float w0 = h1 ? c0.z : c0.y;
        wsum += w0;
        acc.x += w0 * v0.x; acc.y += w0 * v0.y;
        acc.z += w0 * v0.z; acc.w += w0 * v0.w;
    }
    float inv = (end > beg) ? 1.0f / wsum : 0.f;

    float4 b4 = ((const float4*)bias)[lane];
    float4 x;
    x.x = acc.x * inv + b4.x; x.y = acc.y * inv + b4.y;
    x.z = acc.z * inv + b4.z; x.w = acc.w * inv + b4.w;

    float s = x.x + x.y + x.z + x.w;
#pragma unroll
    for (int off = 16; off; off >>= 1) s += __shfl_xor_sync(0xffffffffu, s, off);
    float mu = s * (1.f / 128.f);
    float dx0 = x.x - mu, dx1 = x.y - mu, dx2 = x.z - mu, dx3 = x.w - mu;
    float ss = dx0 * dx0 + dx1 * dx1 + dx2 * dx2 + dx3 * dx3;
#pragma unroll
    for (int off = 16; off; off >>= 1) ss += __shfl_xor_sync(0xffffffffu, ss, off);
    float istd = rsqrtf(ss * (1.f / 128.f) + LN_EPS);

    float4 g4 = ((const float4*)gamma)[lane];
    float4 be4 = ((const float4*)beta)[lane];
    float4 y;
    y.x = g4.x * dx0 * istd + be4.x;
    y.y = g4.y * dx1 * istd + be4.y;
    y.z = g4.z * dx2 * istd + be4.z;
    y.w = g4.w * dx3 * istd + be4.w;
    ((float4*)(out + (size_t)gwarp * 128))[lane] = y;
}

// ---------------- launch ----------------
extern "C" void kernel_launch(void* const* d_in, const int* in_sizes, int n_in,
                              void* d_out, int out_size) {
    const float* h      = (const float*)d_in[0];
    const int*   src    = (const int*)d_in[1];
    const int*   dst    = (const int*)d_in[2];
    const float* W      = (const float*)d_in[3];
    const float* attn_l = (const float*)d_in[4];
    const float* attn_r = (const float*)d_in[5];
    const float* bias   = (const float*)d_in[6];
    const float* gamma  = (const float*)d_in[7];
    const float* beta   = (const float*)d_in[8];
    float* out = (float*)d_out;

    cudaFuncSetAttribute(gemm_tc_kernel, cudaFuncAttributeMaxDynamicSharedMemorySize, SM_TOTAL);

    // order chosen so ncu -s 5 profiles gemm_tc_kernel
    zero_deg_kernel<<<(NN + 255) / 256, 256>>>();
    hist_kernel<<<(EE + 255) / 256, 256>>>(dst);
    chunk_sum_kernel<<<NCHUNK, 256>>>();
    scan_chunks_kernel<<<1, 128>>>();
    scan_final_kernel<<<NCHUNK, 1024>>>();
    gemm_tc_kernel<<<(NN + 127) / 128, 256, SM_TOTAL>>>(h, W, attn_l, attn_r);
    scatter_kernel<<<(EE + 255) / 256, 256>>>(src, dst);
    agg_ln_kernel<<<(NN * 32 + 255) / 256, 256>>>(bias, gamma, beta, out);
}

// round 5
// speedup vs baseline: 1.2329x; 1.2329x over previous
#include <cuda_runtime.h>
#include <cuda_fp16.h>
#include <cstdint>

#define NN 100000
#define EE 1600000
#define NEG_SLOPE 0.2f
#define LN_EPS 1e-5f
#define NCHUNK 98  // ceil(NN/1024)

// ---------------- scratch (device globals; no allocation allowed) ----------------
__device__ __half  g_feat16[(size_t)NN * 128]; // h @ W in fp16 (25.6 MB, L2-resident)
__device__ float   g_el[NN * 2];
__device__ float   g_er[NN * 2];
__device__ int     g_deg[NN];
__device__ int     g_rowptr[NN + 1];
__device__ int     g_cursor[NN];
__device__ int     g_chunk_sum[128];
__device__ int     g_chunk_excl[128];
__device__ float4  g_csr[EE];                  // {src(bits), exp_e_head0, exp_e_head1, pad}

// ---------------- 0: zero degree counters ----------------
__global__ void zero_deg_kernel() {
    int i = blockIdx.x * blockDim.x + threadIdx.x;
    if (i < NN) g_deg[i] = 0;
}

// ---------------- 1: feat = h@W + el/er dots (FFMA, known-good R2 version) ----------------
// Block = 64 rows x 128 cols, 256 threads (8 warps). K tiled by 32.
// h tile transposed in smem -> per-k 'a' reads are warp-broadcast; W reads conflict-free.
#define KT 32
#define HS 68   // padded row stride (floats) for transposed h tile
__global__ void gemm_kernel(const float* __restrict__ h, const float* __restrict__ W,
                            const float* __restrict__ attn_l, const float* __restrict__ attn_r) {
    __shared__ float Wsh[KT * 128];   // 16 KB
    __shared__ float hsh[KT * HS];    // 8.7 KB
    int tid = threadIdx.x;
    int lane = tid & 31, wid = tid >> 5;
    int row0 = blockIdx.x * 64;

    float4 acc[8];
#pragma unroll
    for (int r = 0; r < 8; r++) acc[r] = make_float4(0.f, 0.f, 0.f, 0.f);

    for (int t = 0; t < 4; t++) {
        __syncthreads();
        {
            const float4* Wg = (const float4*)(W + t * KT * 128);
            float4* Ws = (float4*)Wsh;
            for (int j = tid; j < KT * 32; j += 256) Ws[j] = Wg[j];
        }
        for (int j = tid; j < 64 * (KT / 4); j += 256) {
            int r = j >> 3, c4 = j & 7;
            int row = row0 + r;
            float4 v = make_float4(0.f, 0.f, 0.f, 0.f);
            if (row < NN) v = *(const float4*)(h + (size_t)row * 128 + t * KT + c4 * 4);
            hsh[(c4 * 4 + 0) * HS + r] = v.x;
            hsh[(c4 * 4 + 1) * HS + r] = v.y;
            hsh[(c4 * 4 + 2) * HS + r] = v.z;
            hsh[(c4 * 4 + 3) * HS + r] = v.w;
        }
        __syncthreads();
#pragma unroll 4
        for (int kk = 0; kk < KT; kk++) {
            float4 b  = ((const float4*)(Wsh + kk * 128))[lane];
            float4 alo = *(const float4*)(hsh + kk * HS + wid * 8);
            float4 ahi = *(const float4*)(hsh + kk * HS + wid * 8 + 4);
            acc[0].x += alo.x * b.x; acc[0].y += alo.x * b.y; acc[0].z += alo.x * b.z; acc[0].w += alo.x * b.w;
            acc[1].x += alo.y * b.x; acc[1].y += alo.y * b.y; acc[1].z += alo.y * b.z; acc[1].w += alo.y * b.w;
            acc[2].x += alo.z * b.x; acc[2].y += alo.z * b.y; acc[2].z += alo.z * b.z; acc[2].w += alo.z * b.w;
            acc[3].x += alo.w * b.x; acc[3].y += alo.w * b.y; acc[3].z += alo.w * b.z; acc[3].w += alo.w * b.w;
            acc[4].x += ahi.x * b.x; acc[4].y += ahi.x * b.y; acc[4].z += ahi.x * b.z; acc[4].w += ahi.x * b.w;
            acc[5].x += ahi.y * b.x; acc[5].y += ahi.y * b.y; acc[5].z += ahi.y * b.z; acc[5].w += ahi.y * b.w;
            acc[6].x += ahi.z * b.x; acc[6].y += ahi.z * b.y; acc[6].z += ahi.z * b.z; acc[6].w += ahi.z * b.w;
            acc[7].x += ahi.w * b.x; acc[7].y += ahi.w * b.y; acc[7].z += ahi.w * b.z; acc[7].w += ahi.w * b.w;
        }
    }

    // epilogue: store feat (fp16) + per-head attention dots (fp32, from registers)
    float4 al4 = ((const float4*)attn_l)[lane];
    float4 ar4 = ((const float4*)attn_r)[lane];
#pragma unroll
    for (int r = 0; r < 8; r++) {
        int row = row0 + wid * 8 + r;
        if (row >= NN) continue;
        __half2 p0 = __floats2half2_rn(acc[r].x, acc[r].y);
        __half2 p1 = __floats2half2_rn(acc[r].z, acc[r].w);
        uint2 hv;
        hv.x = *(uint32_t*)&p0;
        hv.y = *(uint32_t*)&p1;
        *(uint2*)(g_feat16 + (size_t)row * 128 + lane * 4) = hv;
        float elp = acc[r].x * al4.x + acc[r].y * al4.y + acc[r].z * al4.z + acc[r].w * al4.w;
        float erp = acc[r].x * ar4.x + acc[r].y * ar4.y + acc[r].z * ar4.z + acc[r].w * ar4.w;
#pragma unroll
        for (int off = 8; off; off >>= 1) {   // reduce within each 16-lane half (per head)
            elp += __shfl_xor_sync(0xffffffffu, elp, off);
            erp += __shfl_xor_sync(0xffffffffu, erp, off);
        }
        if (lane == 0)       { g_el[2 * row]     = elp; g_er[2 * row]     = erp; }
        else if (lane == 16) { g_el[2 * row + 1] = elp; g_er[2 * row + 1] = erp; }
    }
}

// ---------------- 2: degree histogram ----------------
__global__ void hist_kernel(const int* __restrict__ dst) {
    int e = blockIdx.x * blockDim.x + threadIdx.x;
    if (e < EE) atomicAdd(&g_deg[dst[e]], 1);
}

// ---------------- 3a: per-chunk sums (chunk = 1024) ----------------
__global__ void chunk_sum_kernel() {
    int b = blockIdx.x, t = threadIdx.x;
    int base = b * 1024;
    int s = 0;
    for (int j = t; j < 1024; j += 256) {
        int i = base + j;
        s += (i < NN) ? g_deg[i] : 0;
    }
    __shared__ int sh[8];
#pragma unroll
    for (int off = 16; off; off >>= 1) s += __shfl_xor_sync(0xffffffffu, s, off);
    if ((t & 31) == 0) sh[t >> 5] = s;
    __syncthreads();
    if (t < 32) {
        int v = (t < 8) ? sh[t] : 0;
#pragma unroll
        for (int off = 4; off; off >>= 1) v += __shfl_xor_sync(0xffffffffu, v, off);
        if (t == 0) g_chunk_sum[b] = v;
    }
}

// ---------------- 3b: scan chunk sums (1 block) ----------------
__global__ void scan_chunks_kernel() {
    __shared__ int sh[128];
    int t = threadIdx.x;
    int v = (t < NCHUNK) ? g_chunk_sum[t] : 0;
    sh[t] = v;
    __syncthreads();
    for (int off = 1; off < 128; off <<= 1) {
        int a = (t >= off) ? sh[t - off] : 0;
        __syncthreads();
        sh[t] += a;
        __syncthreads();
    }
    if (t < NCHUNK) g_chunk_excl[t] = sh[t] - v;
}

// ---------------- 3c: finalize row_ptr / cursor ----------------
__global__ void scan_final_kernel() {
    int i = blockIdx.x * 1024 + threadIdx.x;
    int lane = threadIdx.x & 31, wid = threadIdx.x >> 5;
    int v = (i < NN) ? g_deg[i] : 0;
    int x = v;
#pragma unroll
    for (int off = 1; off < 32; off <<= 1) {
        int y = __shfl_up_sync(0xffffffffu, x, off);
        if (lane >= off) x += y;
    }
    __shared__ int sh[32];
    if (lane == 31) sh[wid] = x;
    __syncthreads();
    if (wid == 0) {
        int y = sh[lane];
#pragma unroll
        for (int off = 1; off < 32; off <<= 1) {
            int z = __shfl_up_sync(0xffffffffu, y, off);
            if (lane >= off) y += z;
        }
        sh[lane] = y;
    }
    __syncthreads();
    int incl = x + (wid ? sh[wid - 1] : 0);
    int base = g_chunk_excl[blockIdx.x];
    if (i < NN) {
        int excl = base + incl - v;
        g_rowptr[i] = excl;
        g_cursor[i] = excl;
    }
    if (i == NN - 1) g_rowptr[NN] = base + incl;
}

// ---------------- 4: scatter edges into CSR order with exp(logit) ----------------
__global__ void scatter_kernel(const int* __restrict__ src, const int* __restrict__ dst) {
    int e = blockIdx.x * blockDim.x + threadIdx.x;
    if (e >= EE) return;
    int s = src[e], d = dst[e];
    int p = atomicAdd(&g_cursor[d], 1);
    float e0 = g_el[2 * s]     + g_er[2 * d];
    float e1 = g_el[2 * s + 1] + g_er[2 * d + 1];
    e0 = (e0 > 0.f) ? e0 : NEG_SLOPE * e0;
    e1 = (e1 > 0.f) ? e1 : NEG_SLOPE * e1;
    g_csr[p] = make_float4(__int_as_float(s), __expf(e0), __expf(e1), 0.f);
}

// ---------------- 5: per-node weighted aggregate + fused LayerNorm ----------------
// One warp per node, single pass. Lanes 0-15 = head0 cols (0-63), 16-31 = head1.
// feat gathered in fp16 (uint2 = 4 halves per lane), math in fp32.
__global__ void agg_ln_kernel(const float* __restrict__ bias, const float* __restrict__ gamma,
                              const float* __restrict__ beta, float* __restrict__ out) {
    int gwarp = (blockIdx.x * blockDim.x + threadIdx.x) >> 5;
    int lane = threadIdx.x & 31;
    if (gwarp >= NN) return;
    int beg = g_rowptr[gwarp], end = g_rowptr[gwarp + 1];
    bool h1 = (lane >= 16);

    float4 acc = make_float4(0.f, 0.f, 0.f, 0.f);
    float wsum = 0.f;
    int i = beg;
    for (; i + 2 <= end; i += 2) {
        float4 c0 = g_csr[i], c1 = g_csr[i + 1];
        uint2 u0 = ((const uint2*)(g_feat16 + (size_t)__float_as_int(c0.x) * 128))[lane];
        uint2 u1 = ((const uint2*)(g_feat16 + (size_t)__float_as_int(c1.x) * 128))[lane];
        float2 v0a = __half22float2(*(__half2*)&u0.x);
        float2 v0b = __half22float2(*(__half2*)&u0.y);
        float2 v1a = __half22float2(*(__half2*)&u1.x);
        float2 v1b = __half22float2(*(__half2*)&u1.y);
        float w0 = h1 ? c0.z : c0.y;
        float w1 = h1 ? c1.z : c1.y;
        wsum += w0 + w1;
        acc.x += w0 * v0a.x + w1 * v1a.x;
        acc.y += w0 * v0a.y + w1 * v1a.y;
        acc.z += w0 * v0b.x + w1 * v1b.x;
        acc.w += w0 * v0b.y + w1 * v1b.y;
    }
    if (i < end) {
        float4 c0 = g_csr[i];
        uint2 u0 = ((const uint2*)(g_feat16 + (size_t)__float_as_int(c0.x) * 128))[lane];
        float2 v0a = __half22float2(*(__half2*)&u0.x);
        float2 v0b = __half22float2(*(__half2*)&u0.y);
        float w0 = h1 ? c0.z : c0.y;
        wsum += w0;
        acc.x += w0 * v0a.x; acc.y += w0 * v0a.y;
        acc.z += w0 * v0b.x; acc.w += w0 * v0b.y;
    }
    float inv = (end > beg) ? 1.0f / wsum : 0.f;

    float4 b4 = ((const float4*)bias)[lane];
    float4 x;
    x.x = acc.x * inv + b4.x; x.y = acc.y * inv + b4.y;
    x.z = acc.z * inv + b4.z; x.w = acc.w * inv + b4.w;

    // LayerNorm across the warp's 128 values (4/lane)
    float s = x.x + x.y + x.z + x.w;
#pragma unroll
    for (int off = 16; off; off >>= 1) s += __shfl_xor_sync(0xffffffffu, s, off);
    float mu = s * (1.f / 128.f);
    float dx0 = x.x - mu, dx1 = x.y - mu, dx2 = x.z - mu, dx3 = x.w - mu;
    float ss = dx0 * dx0 + dx1 * dx1 + dx2 * dx2 + dx3 * dx3;
#pragma unroll
    for (int off = 16; off; off >>= 1) ss += __shfl_xor_sync(0xffffffffu, ss, off);
    float istd = rsqrtf(ss * (1.f / 128.f) + LN_EPS);

    float4 g4 = ((const float4*)gamma)[lane];
    float4 be4 = ((const float4*)beta)[lane];
    float4 y;
    y.x = g4.x * dx0 * istd + be4.x;
    y.y = g4.y * dx1 * istd + be4.y;
    y.z = g4.z * dx2 * istd + be4.z;
    y.w = g4.w * dx3 * istd + be4.w;
    ((float4*)(out + (size_t)gwarp * 128))[lane] = y;
}

// ---------------- launch ----------------
extern "C" void kernel_launch(void* const* d_in, const int* in_sizes, int n_in,
                              void* d_out, int out_size) {
    const float* h      = (const float*)d_in[0];
    const int*   src    = (const int*)d_in[1];
    const int*   dst    = (const int*)d_in[2];
    const float* W      = (const float*)d_in[3];
    const float* attn_l = (const float*)d_in[4];
    const float* attn_r = (const float*)d_in[5];
    const float* bias   = (const float*)d_in[6];
    const float* gamma  = (const float*)d_in[7];
    const float* beta   = (const float*)d_in[8];
    float* out = (float*)d_out;

    zero_deg_kernel<<<(NN + 255) / 256, 256>>>();
    gemm_kernel<<<(NN + 63) / 64, 256>>>(h, W, attn_l, attn_r);
    hist_kernel<<<(EE + 255) / 256, 256>>>(dst);
    chunk_sum_kernel<<<NCHUNK, 256>>>();
    scan_chunks_kernel<<<1, 128>>>();
    scan_final_kernel<<<NCHUNK, 1024>>>();
    scatter_kernel<<<(EE + 255) / 256, 256>>>(src, dst);
    agg_ln_kernel<<<(NN * 32 + 255) / 256, 256>>>(bias, gamma, beta, out);
}